// round 5
// baseline (speedup 1.0000x reference)
#include <cuda_runtime.h>
#include <cuda_bf16.h>
#include <math.h>
#include <cstdint>

// ---------------------------------------------------------------------------
// Problem constants: B=2, S=2048, D=1024, H=16, hd=64, FF=4096
// ---------------------------------------------------------------------------
#define M_ROWS 4096          // B*S
#define DMODEL 1024
#define D3     3072
#define DFF    4096
#define NHEADS 16
#define HDIM   64
#define SEQ    2048
#define LN_EPS 1e-5f

// ---------------------------------------------------------------------------
// Scratch (device globals — no runtime allocation allowed)
// ---------------------------------------------------------------------------
__device__ float g_h   [(size_t)M_ROWS * DMODEL];   // LN output (tf32-rounded)
__device__ float g_qkv [(size_t)M_ROWS * D3];       // qkv projection (fp32)
__device__ float g_attn[(size_t)M_ROWS * DMODEL];   // attention output (tf32-rounded)
__device__ float g_ff  [(size_t)M_ROWS * DFF];      // gelu(fc1) output (tf32-rounded)
__device__ float g_wc  [12582912];                  // tf32-rounded weights

// ---------------------------------------------------------------------------
// Helpers
// ---------------------------------------------------------------------------
__device__ __forceinline__ float to_tf32(float x) {
    float r;
    asm("cvt.rna.tf32.f32 %0, %1;" : "=f"(r) : "f"(x));
    return r;
}

__device__ __forceinline__ void mma16n8k8(float* d,
                                          uint32_t a0, uint32_t a1, uint32_t a2, uint32_t a3,
                                          uint32_t b0, uint32_t b1) {
    asm volatile("mma.sync.aligned.m16n8k8.row.col.f32.tf32.tf32.f32 "
                 "{%0,%1,%2,%3}, {%4,%5,%6,%7}, {%8,%9}, {%0,%1,%2,%3};"
                 : "+f"(d[0]), "+f"(d[1]), "+f"(d[2]), "+f"(d[3])
                 : "r"(a0), "r"(a1), "r"(a2), "r"(a3), "r"(b0), "r"(b1));
}

__device__ __forceinline__ void cp_async16(uint32_t saddr, const void* gptr) {
    asm volatile("cp.async.cg.shared.global [%0], [%1], 16;" :: "r"(saddr), "l"(gptr));
}
__device__ __forceinline__ void cp_commit() {
    asm volatile("cp.async.commit_group;" ::: "memory");
}
template<int N>
__device__ __forceinline__ void cp_wait() {
    asm volatile("cp.async.wait_group %0;" :: "n"(N) : "memory");
}

__device__ __forceinline__ uint32_t smem_u32(const void* p) {
    uint32_t a;
    asm("{ .reg .u64 t; cvta.to.shared.u64 t, %1; cvt.u32.u64 %0, t; }"
        : "=r"(a) : "l"(p));
    return a;
}

__device__ __forceinline__ float gelu_exact(float v) {
    return 0.5f * v * (1.0f + erff(v * 0.70710678118654752f));
}

// ---------------------------------------------------------------------------
// Weight tf32-rounding kernel (elementwise, float4)
// ---------------------------------------------------------------------------
__global__ void cvt_tf32_kernel(const float* __restrict__ in,
                                float* __restrict__ out, int n4)
{
    int i = blockIdx.x * 256 + threadIdx.x;
    if (i < n4) {
        float4 v = ((const float4*)in)[i];
        v.x = to_tf32(v.x); v.y = to_tf32(v.y);
        v.z = to_tf32(v.z); v.w = to_tf32(v.w);
        ((float4*)out)[i] = v;
    }
}

// ---------------------------------------------------------------------------
// TF32 mma.sync NT GEMM: C[M,N] = A[M,K] * W[N,K]^T + bias (+ epilogue)
// Tile 128(M) x 256(N), BK=32, 256 threads (8 warps, 2x4), warp tile 64x64.
// 3-stage cp.async pipeline, 1 CTA/SM.
// EPI: 0 = bias, 1 = bias + exact GELU (+tf32 round), 2 = bias + residual add
// SMEM (floats): As[3][128*36] @ 0, Bs[3][256*36] @ 13824  (165888 bytes)
// ---------------------------------------------------------------------------
#define LDS_STRIDE 36      // 32 + 4 pad floats per row
#define A_STG 4608         // 128*36
#define B_STG 9216         // 256*36
#define B_BASE 13824       // 3*A_STG
#define GEMM_SMEM_BYTES ((B_BASE + 3 * B_STG) * 4)

template<int EPI>
__global__ __launch_bounds__(256, 1)
void gemm_mma(const float* __restrict__ A, const float* __restrict__ W,
              const float* __restrict__ bias, const float* __restrict__ res,
              float* __restrict__ C, int M, int N, int K)
{
    extern __shared__ float smem[];
    const uint32_t sbase = smem_u32(smem);

    const int tid  = threadIdx.x;
    const int w    = tid >> 5;
    const int lane = tid & 31;
    const int g    = lane >> 2;     // 0..7
    const int tig  = lane & 3;      // 0..3

    const int bm = blockIdx.y * 128;
    const int bn = blockIdx.x * 256;
    const int rbase = (w & 1) * 64;       // warp M offset (2 warps in M)
    const int cbase = (w >> 1) * 64;      // warp N offset (4 warps in N)

    const int lr = tid >> 3;              // 0..31
    const int lc = tid & 7;               // 0..7 (16B chunk in 128B row)

    const int nst = K >> 5;

    float acc[4][8][4];
    #pragma unroll
    for (int i = 0; i < 4; i++)
        #pragma unroll
        for (int j = 0; j < 8; j++)
            #pragma unroll
            for (int r = 0; r < 4; r++) acc[i][j][r] = 0.f;

    auto load_stage = [&](int s) {
        const int buf = s % 3;
        const int k0 = s << 5;
        const uint32_t dA = sbase + (uint32_t)(buf * A_STG + lr * LDS_STRIDE + lc * 4) * 4;
        const uint32_t dB = sbase + (uint32_t)(B_BASE + buf * B_STG + lr * LDS_STRIDE + lc * 4) * 4;
        const float* Ag = A + (size_t)(bm + lr) * K + k0 + lc * 4;
        const float* Wg = W + (size_t)(bn + lr) * K + k0 + lc * 4;
        #pragma unroll
        for (int it = 0; it < 4; it++)
            cp_async16(dA + it * 32 * LDS_STRIDE * 4, Ag + (size_t)(it * 32) * K);
        #pragma unroll
        for (int it = 0; it < 8; it++)
            cp_async16(dB + it * 32 * LDS_STRIDE * 4, Wg + (size_t)(it * 32) * K);
    };

    load_stage(0);
    cp_commit();
    load_stage(1);
    cp_commit();

    for (int s = 0; s < nst; s++) {
        if (s == nst - 1) cp_wait<0>(); else cp_wait<1>();
        __syncthreads();

        if (s + 2 < nst) {
            load_stage(s + 2);
            cp_commit();
        }

        const uint32_t* Asu = (const uint32_t*)(smem + (s % 3) * A_STG);
        const uint32_t* Bsu = (const uint32_t*)(smem + B_BASE + (s % 3) * B_STG);

        #pragma unroll
        for (int ks = 0; ks < 4; ks++) {
            const int kk = ks * 8;
            uint32_t a[4][4];
            uint32_t b[8][2];
            #pragma unroll
            for (int i = 0; i < 4; i++) {
                const int r0 = rbase + i * 16 + g;
                a[i][0] = Asu[r0 * LDS_STRIDE + kk + tig];
                a[i][1] = Asu[(r0 + 8) * LDS_STRIDE + kk + tig];
                a[i][2] = Asu[r0 * LDS_STRIDE + kk + tig + 4];
                a[i][3] = Asu[(r0 + 8) * LDS_STRIDE + kk + tig + 4];
            }
            #pragma unroll
            for (int j = 0; j < 8; j++) {
                const int c0 = cbase + j * 8 + g;
                b[j][0] = Bsu[c0 * LDS_STRIDE + kk + tig];
                b[j][1] = Bsu[c0 * LDS_STRIDE + kk + tig + 4];
            }
            #pragma unroll
            for (int i = 0; i < 4; i++)
                #pragma unroll
                for (int j = 0; j < 8; j++)
                    mma16n8k8(acc[i][j], a[i][0], a[i][1], a[i][2], a[i][3],
                              b[j][0], b[j][1]);
        }
    }

    // ---- epilogue ----
    #pragma unroll
    for (int i = 0; i < 4; i++) {
        #pragma unroll
        for (int half = 0; half < 2; half++) {
            const size_t row = (size_t)(bm + rbase + i * 16 + g + half * 8);
            float* crow = C + row * N + bn;
            const float* rrow = (EPI == 2) ? (res + row * N + bn) : nullptr;
            #pragma unroll
            for (int j = 0; j < 8; j++) {
                const int col = cbase + j * 8 + 2 * tig;
                float2 b2 = *(const float2*)(bias + bn + col);
                float vx = acc[i][j][half * 2 + 0] + b2.x;
                float vy = acc[i][j][half * 2 + 1] + b2.y;
                if (EPI == 1) {
                    vx = to_tf32(gelu_exact(vx));
                    vy = to_tf32(gelu_exact(vy));
                }
                if (EPI == 2) {
                    float2 r2 = *(const float2*)(rrow + col);
                    vx += r2.x; vy += r2.y;
                }
                float2 o; o.x = vx; o.y = vy;
                *(float2*)(crow + col) = o;
            }
        }
    }
}

// ---------------------------------------------------------------------------
// LayerNorm: one block per row, 256 threads * 4 floats; output tf32-rounded
// ---------------------------------------------------------------------------
__global__ void ln_kernel(const float* __restrict__ x,
                          const float* __restrict__ gamma,
                          const float* __restrict__ beta,
                          float* __restrict__ y)
{
    const int row = blockIdx.x;
    const int t = threadIdx.x;
    const float4* xr = (const float4*)(x + (size_t)row * DMODEL);
    float4 xv = xr[t];

    __shared__ float red[8];
    __shared__ float stats[2];

    float s = xv.x + xv.y + xv.z + xv.w;
    #pragma unroll
    for (int o = 16; o > 0; o >>= 1) s += __shfl_xor_sync(0xffffffffu, s, o);
    if ((t & 31) == 0) red[t >> 5] = s;
    __syncthreads();
    if (t == 0) {
        float tot = 0.f;
        #pragma unroll
        for (int i = 0; i < 8; i++) tot += red[i];
        stats[0] = tot * (1.0f / DMODEL);
    }
    __syncthreads();
    const float mean = stats[0];

    float dx = xv.x - mean, dy = xv.y - mean, dz = xv.z - mean, dw = xv.w - mean;
    float s2 = dx*dx + dy*dy + dz*dz + dw*dw;
    #pragma unroll
    for (int o = 16; o > 0; o >>= 1) s2 += __shfl_xor_sync(0xffffffffu, s2, o);
    if ((t & 31) == 0) red[t >> 5] = s2;
    __syncthreads();
    if (t == 0) {
        float tot = 0.f;
        #pragma unroll
        for (int i = 0; i < 8; i++) tot += red[i];
        stats[1] = rsqrtf(tot * (1.0f / DMODEL) + LN_EPS);
    }
    __syncthreads();
    const float rstd = stats[1];

    float4 g4 = ((const float4*)gamma)[t];
    float4 b4 = ((const float4*)beta)[t];
    float4 o;
    o.x = to_tf32(dx * rstd * g4.x + b4.x);
    o.y = to_tf32(dy * rstd * g4.y + b4.y);
    o.z = to_tf32(dz * rstd * g4.z + b4.z);
    o.w = to_tf32(dw * rstd * g4.w + b4.w);
    ((float4*)(y + (size_t)row * DMODEL))[t] = o;
}

// ---------------------------------------------------------------------------
// Flash attention (causal) on tensor cores (mma.sync tf32). Unchanged (round 4).
// ---------------------------------------------------------------------------
#define ASP 68
#define ATT_SMEM_FLOATS (4 * 64 * ASP + 128)
#define ATT_SMEM_BYTES  (ATT_SMEM_FLOATS * 4)

__global__ __launch_bounds__(256)
void attn_mma_kernel(const float* __restrict__ qkv, float* __restrict__ out)
{
    extern __shared__ float sm[];
    float* Qs = sm;                    // [q][d] 64x68, tf32, pre-scaled
    float* Ks = sm + 64 * ASP;         // [k][d] 64x68, tf32
    float* Vs = sm + 2 * 64 * ASP;     // [k][d] 64x68, tf32
    float* St = sm + 3 * 64 * ASP;     // [k][q] 64x68 (scores, then P in tf32)
    float* scale_s = sm + 4 * 64 * ASP;        // [64]
    float* l_s     = sm + 4 * 64 * ASP + 64;   // [64]

    const int qt = (int)gridDim.x - 1 - (int)blockIdx.x;  // big tiles first
    const int h  = blockIdx.y;
    const int b  = blockIdx.z;
    const int tid = threadIdx.x;
    const int w = tid >> 5, lane = tid & 31;
    const int g = lane >> 2, tig = lane & 3;
    const int rbase = (w & 3) * 16;      // q offset of warp tile
    const int cbase = (w >> 2) * 32;     // k (or d) offset of warp tile

    const size_t rs = D3;
    const float* qbase = qkv + (size_t)b * SEQ * rs + h * HDIM;
    const float* kbase = qbase + DMODEL;
    const float* vbase = qbase + 2 * DMODEL;

    #pragma unroll
    for (int p = 0; p < 4; p++) {
        const int idx = p * 256 + tid;
        const int row = idx >> 4;
        const int quad = idx & 15;
        float4 v = *(const float4*)(qbase + (size_t)(qt * 64 + row) * rs + quad * 4);
        v.x = to_tf32(v.x * 0.125f); v.y = to_tf32(v.y * 0.125f);
        v.z = to_tf32(v.z * 0.125f); v.w = to_tf32(v.w * 0.125f);
        *(float4*)(Qs + row * ASP + quad * 4) = v;
    }

    float m_i = -1e30f, l_i = 0.f;       // owned by threads 0..63 (q = tid)
    float acc[4][4];
    #pragma unroll
    for (int j = 0; j < 4; j++)
        #pragma unroll
        for (int r = 0; r < 4; r++) acc[j][r] = 0.f;

    __syncthreads();

    for (int kt = 0; kt <= qt; kt++) {
        #pragma unroll
        for (int p = 0; p < 4; p++) {
            const int idx = p * 256 + tid;
            const int row = idx >> 4;
            const int quad = idx & 15;
            const size_t goff = (size_t)(kt * 64 + row) * rs + quad * 4;
            float4 kv = *(const float4*)(kbase + goff);
            kv.x = to_tf32(kv.x); kv.y = to_tf32(kv.y);
            kv.z = to_tf32(kv.z); kv.w = to_tf32(kv.w);
            *(float4*)(Ks + row * ASP + quad * 4) = kv;
            float4 vv = *(const float4*)(vbase + goff);
            vv.x = to_tf32(vv.x); vv.y = to_tf32(vv.y);
            vv.z = to_tf32(vv.z); vv.w = to_tf32(vv.w);
            *(float4*)(Vs + row * ASP + quad * 4) = vv;
        }
        __syncthreads();

        float sacc[4][4];
        #pragma unroll
        for (int j = 0; j < 4; j++)
            #pragma unroll
            for (int r = 0; r < 4; r++) sacc[j][r] = 0.f;

        const uint32_t* Qu = (const uint32_t*)Qs;
        const uint32_t* Ku = (const uint32_t*)Ks;
        #pragma unroll
        for (int ks = 0; ks < 8; ks++) {
            const int kk = ks * 8;
            const int r0 = rbase + g;
            uint32_t a0 = Qu[r0 * ASP + kk + tig];
            uint32_t a1 = Qu[(r0 + 8) * ASP + kk + tig];
            uint32_t a2 = Qu[r0 * ASP + kk + tig + 4];
            uint32_t a3 = Qu[(r0 + 8) * ASP + kk + tig + 4];
            #pragma unroll
            for (int j = 0; j < 4; j++) {
                const int c0 = cbase + j * 8 + g;
                uint32_t b0 = Ku[c0 * ASP + kk + tig];
                uint32_t b1 = Ku[c0 * ASP + kk + tig + 4];
                mma16n8k8(sacc[j], a0, a1, a2, a3, b0, b1);
            }
        }

        const bool diag = (kt == qt);
        #pragma unroll
        for (int j = 0; j < 4; j++) {
            const int k0 = cbase + j * 8 + 2 * tig;
            const int q0 = rbase + g;
            float v00 = sacc[j][0], v01 = sacc[j][1];
            float v10 = sacc[j][2], v11 = sacc[j][3];
            if (diag) {
                if (k0     > q0    ) v00 = -1e30f;
                if (k0 + 1 > q0    ) v01 = -1e30f;
                if (k0     > q0 + 8) v10 = -1e30f;
                if (k0 + 1 > q0 + 8) v11 = -1e30f;
            }
            St[k0       * ASP + q0    ] = v00;
            St[(k0 + 1) * ASP + q0    ] = v01;
            St[k0       * ASP + q0 + 8] = v10;
            St[(k0 + 1) * ASP + q0 + 8] = v11;
        }
        __syncthreads();

        if (tid < 64) {
            float mx = m_i;
            #pragma unroll 8
            for (int k = 0; k < 64; k++) mx = fmaxf(mx, St[k * ASP + tid]);
            const float fac = __expf(m_i - mx);
            float lsum = 0.f;
            #pragma unroll 8
            for (int k = 0; k < 64; k++) {
                float p = __expf(St[k * ASP + tid] - mx);
                St[k * ASP + tid] = to_tf32(p);
                lsum += p;
            }
            m_i = mx;
            l_i = l_i * fac + lsum;
            scale_s[tid] = fac;
        }
        __syncthreads();

        const float f0 = scale_s[rbase + g];
        const float f1 = scale_s[rbase + g + 8];
        #pragma unroll
        for (int j = 0; j < 4; j++) {
            acc[j][0] *= f0; acc[j][1] *= f0;
            acc[j][2] *= f1; acc[j][3] *= f1;
        }

        const uint32_t* Pu = (const uint32_t*)St;
        const uint32_t* Vu = (const uint32_t*)Vs;
        #pragma unroll
        for (int ks = 0; ks < 8; ks++) {
            const int kk = ks * 8;
            const int r0 = rbase + g;
            uint32_t a0 = Pu[(kk + tig)     * ASP + r0];
            uint32_t a1 = Pu[(kk + tig)     * ASP + r0 + 8];
            uint32_t a2 = Pu[(kk + tig + 4) * ASP + r0];
            uint32_t a3 = Pu[(kk + tig + 4) * ASP + r0 + 8];
            #pragma unroll
            for (int j = 0; j < 4; j++) {
                const int c0 = cbase + j * 8 + g;
                uint32_t b0 = Vu[(kk + tig)     * ASP + c0];
                uint32_t b1 = Vu[(kk + tig + 4) * ASP + c0];
                mma16n8k8(acc[j], a0, a1, a2, a3, b0, b1);
            }
        }
        __syncthreads();
    }

    if (tid < 64) l_s[tid] = l_i;
    __syncthreads();

    const float inv0 = 1.0f / l_s[rbase + g];
    const float inv1 = 1.0f / l_s[rbase + g + 8];
    const size_t row0 = (size_t)(b * SEQ + qt * 64 + rbase + g);
    #pragma unroll
    for (int j = 0; j < 4; j++) {
        const int col = h * HDIM + cbase + j * 8 + 2 * tig;
        float2 o0, o1;
        o0.x = to_tf32(acc[j][0] * inv0);
        o0.y = to_tf32(acc[j][1] * inv0);
        o1.x = to_tf32(acc[j][2] * inv1);
        o1.y = to_tf32(acc[j][3] * inv1);
        *(float2*)(out + row0 * DMODEL + col) = o0;
        *(float2*)(out + (row0 + 8) * DMODEL + col) = o1;
    }
}

// ---------------------------------------------------------------------------
// Launch
// ---------------------------------------------------------------------------
extern "C" void kernel_launch(void* const* d_in, const int* in_sizes, int n_in,
                              void* d_out, int out_size)
{
    const float* x     = (const float*)d_in[0];
    const float* ln1_g = (const float*)d_in[1];
    const float* ln1_b = (const float*)d_in[2];
    const float* qkv_w = (const float*)d_in[3];
    const float* qkv_b = (const float*)d_in[4];
    const float* out_w = (const float*)d_in[5];
    const float* out_b = (const float*)d_in[6];
    const float* ln2_g = (const float*)d_in[7];
    const float* ln2_b = (const float*)d_in[8];
    const float* fc1_w = (const float*)d_in[9];
    const float* fc1_b = (const float*)d_in[10];
    const float* fc2_w = (const float*)d_in[11];
    const float* fc2_b = (const float*)d_in[12];
    float* out = (float*)d_out;

    float *h, *qkv, *attn, *ff, *wc;
    cudaGetSymbolAddress((void**)&h,    g_h);
    cudaGetSymbolAddress((void**)&qkv,  g_qkv);
    cudaGetSymbolAddress((void**)&attn, g_attn);
    cudaGetSymbolAddress((void**)&ff,   g_ff);
    cudaGetSymbolAddress((void**)&wc,   g_wc);

    float* wq = wc;                 // 3M
    float* wo = wc + 3145728;       // 1M
    float* w1 = wc + 4194304;       // 4M
    float* w2 = wc + 8388608;       // 4M

    cudaFuncSetAttribute(attn_mma_kernel,
                         cudaFuncAttributeMaxDynamicSharedMemorySize, ATT_SMEM_BYTES);
    cudaFuncSetAttribute(gemm_mma<0>,
                         cudaFuncAttributeMaxDynamicSharedMemorySize, GEMM_SMEM_BYTES);
    cudaFuncSetAttribute(gemm_mma<1>,
                         cudaFuncAttributeMaxDynamicSharedMemorySize, GEMM_SMEM_BYTES);
    cudaFuncSetAttribute(gemm_mma<2>,
                         cudaFuncAttributeMaxDynamicSharedMemorySize, GEMM_SMEM_BYTES);

    // 0) tf32-round the weights
    cvt_tf32_kernel<<<(D3*DMODEL/4 + 255)/256, 256>>>(qkv_w, wq, D3*DMODEL/4);
    cvt_tf32_kernel<<<(DMODEL*DMODEL/4 + 255)/256, 256>>>(out_w, wo, DMODEL*DMODEL/4);
    cvt_tf32_kernel<<<(DFF*DMODEL/4 + 255)/256, 256>>>(fc1_w, w1, DFF*DMODEL/4);
    cvt_tf32_kernel<<<(DMODEL*DFF/4 + 255)/256, 256>>>(fc2_w, w2, DMODEL*DFF/4);

    // 1) h = tf32(LN1(x))
    ln_kernel<<<M_ROWS, 256>>>(x, ln1_g, ln1_b, h);

    // 2) qkv = h @ wq^T + qkv_b
    gemm_mma<0><<<dim3(D3 / 256, M_ROWS / 128), 256, GEMM_SMEM_BYTES>>>(
        h, wq, qkv_b, nullptr, qkv, M_ROWS, D3, DMODEL);

    // 3) attn = tf32(causal_flash_attention(qkv))  [tensor cores]
    attn_mma_kernel<<<dim3(SEQ / 64, NHEADS, 2), 256, ATT_SMEM_BYTES>>>(qkv, attn);

    // 4) x1 = attn @ wo^T + out_b + x
    gemm_mma<2><<<dim3(DMODEL / 256, M_ROWS / 128), 256, GEMM_SMEM_BYTES>>>(
        attn, wo, out_b, x, out, M_ROWS, DMODEL, DMODEL);

    // 5) h = tf32(LN2(x1))
    ln_kernel<<<M_ROWS, 256>>>(out, ln2_g, ln2_b, h);

    // 6) ff = tf32(gelu(h @ w1^T + fc1_b))
    gemm_mma<1><<<dim3(DFF / 256, M_ROWS / 128), 256, GEMM_SMEM_BYTES>>>(
        h, w1, fc1_b, nullptr, ff, M_ROWS, DFF, DMODEL);

    // 7) out = ff @ w2^T + fc2_b + x1
    gemm_mma<2><<<dim3(DMODEL / 256, M_ROWS / 128), 256, GEMM_SMEM_BYTES>>>(
        ff, w2, fc2_b, out, out, M_ROWS, DMODEL, DFF);
}

// round 6
// speedup vs baseline: 1.5731x; 1.5731x over previous
#include <cuda_runtime.h>
#include <cuda_fp16.h>
#include <math.h>
#include <cstdint>

// ---------------------------------------------------------------------------
// Problem constants: B=2, S=2048, D=1024, H=16, hd=64, FF=4096
// ---------------------------------------------------------------------------
#define M_ROWS 4096          // B*S
#define DMODEL 1024
#define D3     3072
#define DFF    4096
#define NHEADS 16
#define HDIM   64
#define SEQ    2048
#define LN_EPS 1e-5f

// ---------------------------------------------------------------------------
// Scratch (device globals — no runtime allocation allowed)
// ---------------------------------------------------------------------------
__device__ __half g_h   [(size_t)M_ROWS * DMODEL];   // LN output (fp16)
__device__ __half g_qkv [(size_t)M_ROWS * D3];       // qkv projection (fp16)
__device__ __half g_attn[(size_t)M_ROWS * DMODEL];   // attention output (fp16)
__device__ __half g_ff  [(size_t)M_ROWS * DFF];      // gelu(fc1) output (fp16)
__device__ __half g_wc  [12582912];                  // fp16 weights

// ---------------------------------------------------------------------------
// Helpers
// ---------------------------------------------------------------------------
__device__ __forceinline__ void mma_h(float* d,
                                      uint32_t a0, uint32_t a1, uint32_t a2, uint32_t a3,
                                      uint32_t b0, uint32_t b1) {
    asm volatile("mma.sync.aligned.m16n8k16.row.col.f32.f16.f16.f32 "
                 "{%0,%1,%2,%3}, {%4,%5,%6,%7}, {%8,%9}, {%0,%1,%2,%3};"
                 : "+f"(d[0]), "+f"(d[1]), "+f"(d[2]), "+f"(d[3])
                 : "r"(a0), "r"(a1), "r"(a2), "r"(a3), "r"(b0), "r"(b1));
}

__device__ __forceinline__ void cp_async16(uint32_t saddr, const void* gptr) {
    asm volatile("cp.async.cg.shared.global [%0], [%1], 16;" :: "r"(saddr), "l"(gptr));
}
__device__ __forceinline__ void cp_commit() {
    asm volatile("cp.async.commit_group;" ::: "memory");
}
template<int N>
__device__ __forceinline__ void cp_wait() {
    asm volatile("cp.async.wait_group %0;" :: "n"(N) : "memory");
}

__device__ __forceinline__ uint32_t smem_u32(const void* p) {
    uint32_t a;
    asm("{ .reg .u64 t; cvta.to.shared.u64 t, %1; cvt.u32.u64 %0, t; }"
        : "=r"(a) : "l"(p));
    return a;
}

__device__ __forceinline__ float gelu_exact(float v) {
    return 0.5f * v * (1.0f + erff(v * 0.70710678118654752f));
}

// ---------------------------------------------------------------------------
// Weight fp32 -> fp16 conversion (8 elements / thread)
// ---------------------------------------------------------------------------
__global__ void cvt_f2h(const float* __restrict__ in, __half* __restrict__ out, int n8)
{
    int i = blockIdx.x * 256 + threadIdx.x;
    if (i < n8) {
        float4 a = ((const float4*)in)[2 * i];
        float4 b = ((const float4*)in)[2 * i + 1];
        __half2 h0 = __floats2half2_rn(a.x, a.y);
        __half2 h1 = __floats2half2_rn(a.z, a.w);
        __half2 h2 = __floats2half2_rn(b.x, b.y);
        __half2 h3 = __floats2half2_rn(b.z, b.w);
        uint4 o;
        o.x = *(uint32_t*)&h0; o.y = *(uint32_t*)&h1;
        o.z = *(uint32_t*)&h2; o.w = *(uint32_t*)&h3;
        ((uint4*)out)[i] = o;
    }
}

// ---------------------------------------------------------------------------
// FP16 mma.sync NT GEMM: C[M,N] = A[M,K] * W[N,K]^T + bias (+ epilogue)
// Tile 128(M) x 256(N), BK=64 halves, 256 threads (8 warps 2x4), warp 64x64.
// 3-stage cp.async pipeline, 1 CTA/SM. fp32 accumulate.
// EPI: 0 = bias (half out), 1 = bias + exact GELU (half out),
//      2 = bias + residual add (float out)
// SMEM u32 layout: As[3][128*36] @ 0, Bs[3][256*36] @ 13824
// ---------------------------------------------------------------------------
#define LDS_STRIDE 36      // u32 per row: 32 data (64 halves) + 4 pad
#define A_STG 4608         // 128*36 u32
#define B_STG 9216         // 256*36 u32
#define B_BASE 13824       // 3*A_STG
#define GEMM_SMEM_BYTES ((B_BASE + 3 * B_STG) * 4)

template<int EPI, typename OT>
__global__ __launch_bounds__(256, 1)
void gemm_h(const __half* __restrict__ A, const __half* __restrict__ W,
            const float* __restrict__ bias, const float* __restrict__ res,
            OT* __restrict__ C, int M, int N, int K)
{
    extern __shared__ uint32_t smem[];
    const uint32_t sbase = smem_u32(smem);

    const int tid  = threadIdx.x;
    const int w    = tid >> 5;
    const int lane = tid & 31;
    const int g    = lane >> 2;     // 0..7
    const int tig  = lane & 3;      // 0..3

    const int bm = blockIdx.y * 128;
    const int bn = blockIdx.x * 256;
    const int rbase = (w & 1) * 64;       // warp M offset
    const int cbase = (w >> 1) * 64;      // warp N offset

    const int lr = tid >> 3;              // 0..31
    const int lc = tid & 7;               // 0..7 (16B = 8-half chunk)

    const int nst = K >> 6;               // BK = 64 halves

    float acc[4][8][4];
    #pragma unroll
    for (int i = 0; i < 4; i++)
        #pragma unroll
        for (int j = 0; j < 8; j++)
            #pragma unroll
            for (int r = 0; r < 4; r++) acc[i][j][r] = 0.f;

    auto load_stage = [&](int s) {
        const int buf = s % 3;
        const int k0 = s << 6;
        const uint32_t dA = sbase + (uint32_t)(buf * A_STG + lr * LDS_STRIDE + lc * 4) * 4;
        const uint32_t dB = sbase + (uint32_t)(B_BASE + buf * B_STG + lr * LDS_STRIDE + lc * 4) * 4;
        const __half* Ag = A + (size_t)(bm + lr) * K + k0 + lc * 8;
        const __half* Wg = W + (size_t)(bn + lr) * K + k0 + lc * 8;
        #pragma unroll
        for (int it = 0; it < 4; it++)
            cp_async16(dA + it * 32 * LDS_STRIDE * 4, Ag + (size_t)(it * 32) * K);
        #pragma unroll
        for (int it = 0; it < 8; it++)
            cp_async16(dB + it * 32 * LDS_STRIDE * 4, Wg + (size_t)(it * 32) * K);
    };

    load_stage(0);
    cp_commit();
    load_stage(1);
    cp_commit();

    for (int s = 0; s < nst; s++) {
        if (s == nst - 1) cp_wait<0>(); else cp_wait<1>();
        __syncthreads();

        if (s + 2 < nst) {
            load_stage(s + 2);
            cp_commit();
        }

        const uint32_t* Asu = smem + (s % 3) * A_STG;
        const uint32_t* Bsu = smem + B_BASE + (s % 3) * B_STG;

        #pragma unroll
        for (int ks = 0; ks < 4; ks++) {      // 4 k-steps of 16 halves
            const int kk = ks * 8;            // u32 offset within row
            uint32_t a[4][4];
            uint32_t b[8][2];
            #pragma unroll
            for (int i = 0; i < 4; i++) {
                const int r0 = rbase + i * 16 + g;
                a[i][0] = Asu[r0 * LDS_STRIDE + kk + tig];
                a[i][1] = Asu[(r0 + 8) * LDS_STRIDE + kk + tig];
                a[i][2] = Asu[r0 * LDS_STRIDE + kk + tig + 4];
                a[i][3] = Asu[(r0 + 8) * LDS_STRIDE + kk + tig + 4];
            }
            #pragma unroll
            for (int j = 0; j < 8; j++) {
                const int c0 = cbase + j * 8 + g;
                b[j][0] = Bsu[c0 * LDS_STRIDE + kk + tig];
                b[j][1] = Bsu[c0 * LDS_STRIDE + kk + tig + 4];
            }
            #pragma unroll
            for (int i = 0; i < 4; i++)
                #pragma unroll
                for (int j = 0; j < 8; j++)
                    mma_h(acc[i][j], a[i][0], a[i][1], a[i][2], a[i][3],
                          b[j][0], b[j][1]);
        }
    }

    // ---- epilogue ----
    #pragma unroll
    for (int i = 0; i < 4; i++) {
        #pragma unroll
        for (int half_ = 0; half_ < 2; half_++) {
            const size_t row = (size_t)(bm + rbase + i * 16 + g + half_ * 8);
            OT* crow = C + row * N + bn;
            const float* rrow = (EPI == 2) ? (res + row * N + bn) : nullptr;
            #pragma unroll
            for (int j = 0; j < 8; j++) {
                const int col = cbase + j * 8 + 2 * tig;
                float2 b2 = *(const float2*)(bias + bn + col);
                float vx = acc[i][j][half_ * 2 + 0] + b2.x;
                float vy = acc[i][j][half_ * 2 + 1] + b2.y;
                if (EPI == 1) { vx = gelu_exact(vx); vy = gelu_exact(vy); }
                if constexpr (EPI == 2) {
                    float2 r2 = *(const float2*)(rrow + col);
                    float2 o; o.x = vx + r2.x; o.y = vy + r2.y;
                    *(float2*)((float*)crow + col) = o;
                } else {
                    __half2 hv = __floats2half2_rn(vx, vy);
                    *(__half2*)((__half*)crow + col) = hv;
                }
            }
        }
    }
}

// ---------------------------------------------------------------------------
// LayerNorm: one block per row, 256 threads * 4 floats; fp16 output
// ---------------------------------------------------------------------------
__global__ void ln_kernel(const float* __restrict__ x,
                          const float* __restrict__ gamma,
                          const float* __restrict__ beta,
                          __half* __restrict__ y)
{
    const int row = blockIdx.x;
    const int t = threadIdx.x;
    const float4* xr = (const float4*)(x + (size_t)row * DMODEL);
    float4 xv = xr[t];

    __shared__ float red[8];
    __shared__ float stats[2];

    float s = xv.x + xv.y + xv.z + xv.w;
    #pragma unroll
    for (int o = 16; o > 0; o >>= 1) s += __shfl_xor_sync(0xffffffffu, s, o);
    if ((t & 31) == 0) red[t >> 5] = s;
    __syncthreads();
    if (t == 0) {
        float tot = 0.f;
        #pragma unroll
        for (int i = 0; i < 8; i++) tot += red[i];
        stats[0] = tot * (1.0f / DMODEL);
    }
    __syncthreads();
    const float mean = stats[0];

    float dx = xv.x - mean, dy = xv.y - mean, dz = xv.z - mean, dw = xv.w - mean;
    float s2 = dx*dx + dy*dy + dz*dz + dw*dw;
    #pragma unroll
    for (int o = 16; o > 0; o >>= 1) s2 += __shfl_xor_sync(0xffffffffu, s2, o);
    if ((t & 31) == 0) red[t >> 5] = s2;
    __syncthreads();
    if (t == 0) {
        float tot = 0.f;
        #pragma unroll
        for (int i = 0; i < 8; i++) tot += red[i];
        stats[1] = rsqrtf(tot * (1.0f / DMODEL) + LN_EPS);
    }
    __syncthreads();
    const float rstd = stats[1];

    float4 g4 = ((const float4*)gamma)[t];
    float4 b4 = ((const float4*)beta)[t];
    __half2 h0 = __floats2half2_rn(dx * rstd * g4.x + b4.x, dy * rstd * g4.y + b4.y);
    __half2 h1 = __floats2half2_rn(dz * rstd * g4.z + b4.z, dw * rstd * g4.w + b4.w);
    uint2 o; o.x = *(uint32_t*)&h0; o.y = *(uint32_t*)&h1;
    ((uint2*)(y + (size_t)row * DMODEL))[t] = o;
}

// ---------------------------------------------------------------------------
// Flash attention (causal), fp16 mma. One block per (q-tile 64, head, batch).
// 256 threads = 8 warps in 4(q) x 2(k/d). Scores fp32 in SMEM; P fp16.
// SMEM (bytes): Qs[64x72h]@0, Ks@9216, Vt[64x72h d-major]@18432,
//               St[64x68f]@27648, Ph[64x72h]@45056, scale@54272, l@54528
// ---------------------------------------------------------------------------
#define ASP 68
#define ATT_SMEM_BYTES 54784

__global__ __launch_bounds__(256)
void attn_h_kernel(const __half* __restrict__ qkv, __half* __restrict__ out)
{
    extern __shared__ char smc[];
    __half* Qs = (__half*)smc;                    // [q][d] 64x72
    __half* Ks = (__half*)(smc + 9216);           // [k][d] 64x72
    __half* Vt = (__half*)(smc + 18432);          // [d][k] 64x72 (transposed)
    float*  St = (float*)(smc + 27648);           // [k][q] 64x68
    __half* Ph = (__half*)(smc + 45056);          // [q][k] 64x72
    float* scale_s = (float*)(smc + 54272);       // [64]
    float* l_s     = (float*)(smc + 54528);       // [64]

    const int qt = (int)gridDim.x - 1 - (int)blockIdx.x;
    const int h  = blockIdx.y;
    const int b  = blockIdx.z;
    const int tid = threadIdx.x;
    const int w = tid >> 5, lane = tid & 31;
    const int g = lane >> 2, tig = lane & 3;
    const int rbase = (w & 3) * 16;      // q offset of warp tile
    const int cbase = (w >> 2) * 32;     // k (or d) offset of warp tile

    const size_t rs = D3;
    const __half* qbase = qkv + (size_t)b * SEQ * rs + h * HDIM;
    const __half* kbase = qbase + DMODEL;
    const __half* vbase = qbase + 2 * DMODEL;

    // ---- load Q tile (scaled by 1/8 exactly) ----
    {
        const __half2 s2 = __float2half2_rn(0.125f);
        #pragma unroll
        for (int p = 0; p < 2; p++) {
            const int idx = p * 256 + tid;
            const int row = idx >> 3;
            const int ch = idx & 7;
            uint4 v = *(const uint4*)(qbase + (size_t)(qt * 64 + row) * rs + ch * 8);
            __half2* hv = (__half2*)&v;
            hv[0] = __hmul2(hv[0], s2); hv[1] = __hmul2(hv[1], s2);
            hv[2] = __hmul2(hv[2], s2); hv[3] = __hmul2(hv[3], s2);
            *(uint4*)(Qs + row * 72 + ch * 8) = v;
        }
    }

    float m_i = -1e30f, l_i = 0.f;       // owned by threads 0..63 (q = tid)
    float acc[4][4];
    #pragma unroll
    for (int j = 0; j < 4; j++)
        #pragma unroll
        for (int r = 0; r < 4; r++) acc[j][r] = 0.f;

    __syncthreads();

    for (int kt = 0; kt <= qt; kt++) {
        // ---- load K (natural), V (transposed) ----
        #pragma unroll
        for (int p = 0; p < 2; p++) {
            const int idx = p * 256 + tid;
            const int row = idx >> 3;     // k index
            const int ch = idx & 7;
            const size_t goff = (size_t)(kt * 64 + row) * rs + ch * 8;
            uint4 kv = *(const uint4*)(kbase + goff);
            *(uint4*)(Ks + row * 72 + ch * 8) = kv;
            uint4 vv = *(const uint4*)(vbase + goff);
            const __half* hv = (const __half*)&vv;
            #pragma unroll
            for (int j = 0; j < 8; j++)
                Vt[(ch * 8 + j) * 72 + row] = hv[j];
        }
        __syncthreads();

        // ---- S = Q K^T : warp tile 16(q) x 32(k), 4 k16-steps over d ----
        float sacc[4][4];
        #pragma unroll
        for (int j = 0; j < 4; j++)
            #pragma unroll
            for (int r = 0; r < 4; r++) sacc[j][r] = 0.f;

        const uint32_t* Qu = (const uint32_t*)Qs;
        const uint32_t* Ku = (const uint32_t*)Ks;
        #pragma unroll
        for (int ks = 0; ks < 4; ks++) {
            const int kk = ks * 8;
            const int r0 = rbase + g;
            uint32_t a0 = Qu[r0 * 36 + kk + tig];
            uint32_t a1 = Qu[(r0 + 8) * 36 + kk + tig];
            uint32_t a2 = Qu[r0 * 36 + kk + tig + 4];
            uint32_t a3 = Qu[(r0 + 8) * 36 + kk + tig + 4];
            #pragma unroll
            for (int j = 0; j < 4; j++) {
                const int c0 = cbase + j * 8 + g;
                uint32_t b0 = Ku[c0 * 36 + kk + tig];
                uint32_t b1 = Ku[c0 * 36 + kk + tig + 4];
                mma_h(sacc[j], a0, a1, a2, a3, b0, b1);
            }
        }

        // ---- store S transposed with causal mask ----
        const bool diag = (kt == qt);
        #pragma unroll
        for (int j = 0; j < 4; j++) {
            const int k0 = cbase + j * 8 + 2 * tig;
            const int q0 = rbase + g;
            float v00 = sacc[j][0], v01 = sacc[j][1];
            float v10 = sacc[j][2], v11 = sacc[j][3];
            if (diag) {
                if (k0     > q0    ) v00 = -1e30f;
                if (k0 + 1 > q0    ) v01 = -1e30f;
                if (k0     > q0 + 8) v10 = -1e30f;
                if (k0 + 1 > q0 + 8) v11 = -1e30f;
            }
            St[k0       * ASP + q0    ] = v00;
            St[(k0 + 1) * ASP + q0    ] = v01;
            St[k0       * ASP + q0 + 8] = v10;
            St[(k0 + 1) * ASP + q0 + 8] = v11;
        }
        __syncthreads();

        // ---- online softmax: thread t (<64) owns q column t; P -> fp16 ----
        if (tid < 64) {
            float mx = m_i;
            #pragma unroll 8
            for (int k = 0; k < 64; k++) mx = fmaxf(mx, St[k * ASP + tid]);
            const float fac = __expf(m_i - mx);
            float lsum = 0.f;
            uint32_t* Pr = (uint32_t*)Ph + tid * 36;
            #pragma unroll 4
            for (int k2 = 0; k2 < 32; k2++) {
                float p0 = __expf(St[(2 * k2)     * ASP + tid] - mx);
                float p1 = __expf(St[(2 * k2 + 1) * ASP + tid] - mx);
                lsum += p0 + p1;
                __half2 hp = __floats2half2_rn(p0, p1);
                Pr[k2] = *(uint32_t*)&hp;
            }
            m_i = mx;
            l_i = l_i * fac + lsum;
            scale_s[tid] = fac;
        }
        __syncthreads();

        // ---- rescale O accumulators ----
        const float f0 = scale_s[rbase + g];
        const float f1 = scale_s[rbase + g + 8];
        #pragma unroll
        for (int j = 0; j < 4; j++) {
            acc[j][0] *= f0; acc[j][1] *= f0;
            acc[j][2] *= f1; acc[j][3] *= f1;
        }

        // ---- O += P V : warp tile 16(q) x 32(d), 4 k16-steps over k ----
        const uint32_t* Pu = (const uint32_t*)Ph;
        const uint32_t* Vu = (const uint32_t*)Vt;
        #pragma unroll
        for (int ks = 0; ks < 4; ks++) {
            const int kk = ks * 8;
            const int r0 = rbase + g;
            uint32_t a0 = Pu[r0 * 36 + kk + tig];
            uint32_t a1 = Pu[(r0 + 8) * 36 + kk + tig];
            uint32_t a2 = Pu[r0 * 36 + kk + tig + 4];
            uint32_t a3 = Pu[(r0 + 8) * 36 + kk + tig + 4];
            #pragma unroll
            for (int j = 0; j < 4; j++) {
                const int c0 = cbase + j * 8 + g;
                uint32_t b0 = Vu[c0 * 36 + kk + tig];
                uint32_t b1 = Vu[c0 * 36 + kk + tig + 4];
                mma_h(acc[j], a0, a1, a2, a3, b0, b1);
            }
        }
        __syncthreads();
    }

    if (tid < 64) l_s[tid] = l_i;
    __syncthreads();

    const float inv0 = 1.0f / l_s[rbase + g];
    const float inv1 = 1.0f / l_s[rbase + g + 8];
    const size_t row0 = (size_t)(b * SEQ + qt * 64 + rbase + g);
    #pragma unroll
    for (int j = 0; j < 4; j++) {
        const int col = h * HDIM + cbase + j * 8 + 2 * tig;
        __half2 o0 = __floats2half2_rn(acc[j][0] * inv0, acc[j][1] * inv0);
        __half2 o1 = __floats2half2_rn(acc[j][2] * inv1, acc[j][3] * inv1);
        *(__half2*)(out + row0 * DMODEL + col) = o0;
        *(__half2*)(out + (row0 + 8) * DMODEL + col) = o1;
    }
}

// ---------------------------------------------------------------------------
// Launch
// ---------------------------------------------------------------------------
extern "C" void kernel_launch(void* const* d_in, const int* in_sizes, int n_in,
                              void* d_out, int out_size)
{
    const float* x     = (const float*)d_in[0];
    const float* ln1_g = (const float*)d_in[1];
    const float* ln1_b = (const float*)d_in[2];
    const float* qkv_w = (const float*)d_in[3];
    const float* qkv_b = (const float*)d_in[4];
    const float* out_w = (const float*)d_in[5];
    const float* out_b = (const float*)d_in[6];
    const float* ln2_g = (const float*)d_in[7];
    const float* ln2_b = (const float*)d_in[8];
    const float* fc1_w = (const float*)d_in[9];
    const float* fc1_b = (const float*)d_in[10];
    const float* fc2_w = (const float*)d_in[11];
    const float* fc2_b = (const float*)d_in[12];
    float* out = (float*)d_out;

    __half *h, *qkv, *attn, *ff, *wc;
    cudaGetSymbolAddress((void**)&h,    g_h);
    cudaGetSymbolAddress((void**)&qkv,  g_qkv);
    cudaGetSymbolAddress((void**)&attn, g_attn);
    cudaGetSymbolAddress((void**)&ff,   g_ff);
    cudaGetSymbolAddress((void**)&wc,   g_wc);

    __half* wq = wc;                 // 3M elems
    __half* wo = wc + 3145728;       // 1M
    __half* w1 = wc + 4194304;       // 4M
    __half* w2 = wc + 8388608;       // 4M

    cudaFuncSetAttribute(attn_h_kernel,
                         cudaFuncAttributeMaxDynamicSharedMemorySize, ATT_SMEM_BYTES);
    cudaFuncSetAttribute((gemm_h<0, __half>),
                         cudaFuncAttributeMaxDynamicSharedMemorySize, GEMM_SMEM_BYTES);
    cudaFuncSetAttribute((gemm_h<1, __half>),
                         cudaFuncAttributeMaxDynamicSharedMemorySize, GEMM_SMEM_BYTES);
    cudaFuncSetAttribute((gemm_h<2, float>),
                         cudaFuncAttributeMaxDynamicSharedMemorySize, GEMM_SMEM_BYTES);

    // 0) convert weights to fp16
    cvt_f2h<<<(D3*DMODEL/8 + 255)/256, 256>>>(qkv_w, wq, D3*DMODEL/8);
    cvt_f2h<<<(DMODEL*DMODEL/8 + 255)/256, 256>>>(out_w, wo, DMODEL*DMODEL/8);
    cvt_f2h<<<(DFF*DMODEL/8 + 255)/256, 256>>>(fc1_w, w1, DFF*DMODEL/8);
    cvt_f2h<<<(DMODEL*DFF/8 + 255)/256, 256>>>(fc2_w, w2, DMODEL*DFF/8);

    // 1) h = fp16(LN1(x))
    ln_kernel<<<M_ROWS, 256>>>(x, ln1_g, ln1_b, h);

    // 2) qkv = h @ wq^T + qkv_b   (fp16 out)
    gemm_h<0, __half><<<dim3(D3 / 256, M_ROWS / 128), 256, GEMM_SMEM_BYTES>>>(
        h, wq, qkv_b, nullptr, qkv, M_ROWS, D3, DMODEL);

    // 3) attn = fp16(causal_flash_attention(qkv))
    attn_h_kernel<<<dim3(SEQ / 64, NHEADS, 2), 256, ATT_SMEM_BYTES>>>(qkv, attn);

    // 4) x1 = attn @ wo^T + out_b + x   (fp32 out)
    gemm_h<2, float><<<dim3(DMODEL / 256, M_ROWS / 128), 256, GEMM_SMEM_BYTES>>>(
        attn, wo, out_b, x, out, M_ROWS, DMODEL, DMODEL);

    // 5) h = fp16(LN2(x1))
    ln_kernel<<<M_ROWS, 256>>>(out, ln2_g, ln2_b, h);

    // 6) ff = fp16(gelu(h @ w1^T + fc1_b))
    gemm_h<1, __half><<<dim3(DFF / 256, M_ROWS / 128), 256, GEMM_SMEM_BYTES>>>(
        h, w1, fc1_b, nullptr, ff, M_ROWS, DFF, DMODEL);

    // 7) out = ff @ w2^T + fc2_b + x1   (fp32 out, in-place residual)
    gemm_h<2, float><<<dim3(DMODEL / 256, M_ROWS / 128), 256, GEMM_SMEM_BYTES>>>(
        ff, w2, fc2_b, out, out, M_ROWS, DMODEL, DFF);
}

// round 7
// speedup vs baseline: 2.0991x; 1.3344x over previous
#include <cuda_runtime.h>
#include <cuda_fp16.h>
#include <math.h>
#include <cstdint>

// ---------------------------------------------------------------------------
// Problem constants: B=2, S=2048, D=1024, H=16, hd=64, FF=4096
// ---------------------------------------------------------------------------
#define M_ROWS 4096          // B*S
#define DMODEL 1024
#define D3     3072
#define DFF    4096
#define NHEADS 16
#define HDIM   64
#define SEQ    2048
#define LN_EPS 1e-5f

// ---------------------------------------------------------------------------
// Scratch (device globals — no runtime allocation allowed)
// ---------------------------------------------------------------------------
__device__ __half g_h   [(size_t)M_ROWS * DMODEL];   // LN output (fp16)
__device__ __half g_qkv [(size_t)M_ROWS * D3];       // qkv projection (fp16)
__device__ __half g_attn[(size_t)M_ROWS * DMODEL];   // attention output (fp16)
__device__ __half g_ff  [(size_t)M_ROWS * DFF];      // gelu(fc1) output (fp16)
__device__ __half g_wc  [12582912];                  // fp16 weights

// ---------------------------------------------------------------------------
// Helpers
// ---------------------------------------------------------------------------
__device__ __forceinline__ void mma_h(float* d,
                                      uint32_t a0, uint32_t a1, uint32_t a2, uint32_t a3,
                                      uint32_t b0, uint32_t b1) {
    asm volatile("mma.sync.aligned.m16n8k16.row.col.f32.f16.f16.f32 "
                 "{%0,%1,%2,%3}, {%4,%5,%6,%7}, {%8,%9}, {%0,%1,%2,%3};"
                 : "+f"(d[0]), "+f"(d[1]), "+f"(d[2]), "+f"(d[3])
                 : "r"(a0), "r"(a1), "r"(a2), "r"(a3), "r"(b0), "r"(b1));
}

__device__ __forceinline__ void ldsm_x4_trans(uint32_t& r0, uint32_t& r1,
                                              uint32_t& r2, uint32_t& r3,
                                              uint32_t addr) {
    asm volatile("ldmatrix.sync.aligned.m8n8.x4.trans.shared.b16 {%0,%1,%2,%3}, [%4];"
                 : "=r"(r0), "=r"(r1), "=r"(r2), "=r"(r3) : "r"(addr));
}

__device__ __forceinline__ void cp_async16(uint32_t saddr, const void* gptr) {
    asm volatile("cp.async.cg.shared.global [%0], [%1], 16;" :: "r"(saddr), "l"(gptr));
}
__device__ __forceinline__ void cp_commit() {
    asm volatile("cp.async.commit_group;" ::: "memory");
}
template<int N>
__device__ __forceinline__ void cp_wait() {
    asm volatile("cp.async.wait_group %0;" :: "n"(N) : "memory");
}

__device__ __forceinline__ uint32_t smem_u32(const void* p) {
    uint32_t a;
    asm("{ .reg .u64 t; cvta.to.shared.u64 t, %1; cvt.u32.u64 %0, t; }"
        : "=r"(a) : "l"(p));
    return a;
}

__device__ __forceinline__ float gelu_exact(float v) {
    return 0.5f * v * (1.0f + erff(v * 0.70710678118654752f));
}

// ---------------------------------------------------------------------------
// Weight fp32 -> fp16 conversion, all 4 weights in ONE launch.
// n8 boundaries (8 elems each): qkv 393216, out +131072, fc1 +524288, fc2 +524288
// ---------------------------------------------------------------------------
__global__ void cvt_all(const float* __restrict__ wa, const float* __restrict__ wb,
                        const float* __restrict__ wcp, const float* __restrict__ wd,
                        __half* __restrict__ out)
{
    int i = blockIdx.x * 256 + threadIdx.x;
    if (i >= 1572864) return;
    const float* src; int off;
    if (i < 393216)       { src = wa;  off = i; }
    else if (i < 524288)  { src = wb;  off = i - 393216; }
    else if (i < 1048576) { src = wcp; off = i - 524288; }
    else                  { src = wd;  off = i - 1048576; }
    float4 a = ((const float4*)src)[2 * off];
    float4 b = ((const float4*)src)[2 * off + 1];
    __half2 h0 = __floats2half2_rn(a.x, a.y);
    __half2 h1 = __floats2half2_rn(a.z, a.w);
    __half2 h2 = __floats2half2_rn(b.x, b.y);
    __half2 h3 = __floats2half2_rn(b.z, b.w);
    uint4 o;
    o.x = *(uint32_t*)&h0; o.y = *(uint32_t*)&h1;
    o.z = *(uint32_t*)&h2; o.w = *(uint32_t*)&h3;
    ((uint4*)out)[i] = o;
}

// ---------------------------------------------------------------------------
// FP16 mma.sync NT GEMM (unchanged from round 6 — rate-bound, known good)
// Tile 128x256, BK=64 halves, 256 threads, warp 64x64, 3-stage cp.async.
// ---------------------------------------------------------------------------
#define LDS_STRIDE 36      // u32 per row: 32 data (64 halves) + 4 pad
#define A_STG 4608
#define B_STG 9216
#define B_BASE 13824
#define GEMM_SMEM_BYTES ((B_BASE + 3 * B_STG) * 4)

template<int EPI, typename OT>
__global__ __launch_bounds__(256, 1)
void gemm_h(const __half* __restrict__ A, const __half* __restrict__ W,
            const float* __restrict__ bias, const float* __restrict__ res,
            OT* __restrict__ C, int M, int N, int K)
{
    extern __shared__ uint32_t smem[];
    const uint32_t sbase = smem_u32(smem);

    const int tid  = threadIdx.x;
    const int w    = tid >> 5;
    const int lane = tid & 31;
    const int g    = lane >> 2;
    const int tig  = lane & 3;

    const int bm = blockIdx.y * 128;
    const int bn = blockIdx.x * 256;
    const int rbase = (w & 1) * 64;
    const int cbase = (w >> 1) * 64;

    const int lr = tid >> 3;
    const int lc = tid & 7;

    const int nst = K >> 6;

    float acc[4][8][4];
    #pragma unroll
    for (int i = 0; i < 4; i++)
        #pragma unroll
        for (int j = 0; j < 8; j++)
            #pragma unroll
            for (int r = 0; r < 4; r++) acc[i][j][r] = 0.f;

    auto load_stage = [&](int s) {
        const int buf = s % 3;
        const int k0 = s << 6;
        const uint32_t dA = sbase + (uint32_t)(buf * A_STG + lr * LDS_STRIDE + lc * 4) * 4;
        const uint32_t dB = sbase + (uint32_t)(B_BASE + buf * B_STG + lr * LDS_STRIDE + lc * 4) * 4;
        const __half* Ag = A + (size_t)(bm + lr) * K + k0 + lc * 8;
        const __half* Wg = W + (size_t)(bn + lr) * K + k0 + lc * 8;
        #pragma unroll
        for (int it = 0; it < 4; it++)
            cp_async16(dA + it * 32 * LDS_STRIDE * 4, Ag + (size_t)(it * 32) * K);
        #pragma unroll
        for (int it = 0; it < 8; it++)
            cp_async16(dB + it * 32 * LDS_STRIDE * 4, Wg + (size_t)(it * 32) * K);
    };

    load_stage(0);
    cp_commit();
    load_stage(1);
    cp_commit();

    for (int s = 0; s < nst; s++) {
        if (s == nst - 1) cp_wait<0>(); else cp_wait<1>();
        __syncthreads();

        if (s + 2 < nst) {
            load_stage(s + 2);
            cp_commit();
        }

        const uint32_t* Asu = smem + (s % 3) * A_STG;
        const uint32_t* Bsu = smem + B_BASE + (s % 3) * B_STG;

        #pragma unroll
        for (int ks = 0; ks < 4; ks++) {
            const int kk = ks * 8;
            uint32_t a[4][4];
            uint32_t b[8][2];
            #pragma unroll
            for (int i = 0; i < 4; i++) {
                const int r0 = rbase + i * 16 + g;
                a[i][0] = Asu[r0 * LDS_STRIDE + kk + tig];
                a[i][1] = Asu[(r0 + 8) * LDS_STRIDE + kk + tig];
                a[i][2] = Asu[r0 * LDS_STRIDE + kk + tig + 4];
                a[i][3] = Asu[(r0 + 8) * LDS_STRIDE + kk + tig + 4];
            }
            #pragma unroll
            for (int j = 0; j < 8; j++) {
                const int c0 = cbase + j * 8 + g;
                b[j][0] = Bsu[c0 * LDS_STRIDE + kk + tig];
                b[j][1] = Bsu[c0 * LDS_STRIDE + kk + tig + 4];
            }
            #pragma unroll
            for (int i = 0; i < 4; i++)
                #pragma unroll
                for (int j = 0; j < 8; j++)
                    mma_h(acc[i][j], a[i][0], a[i][1], a[i][2], a[i][3],
                          b[j][0], b[j][1]);
        }
    }

    #pragma unroll
    for (int i = 0; i < 4; i++) {
        #pragma unroll
        for (int half_ = 0; half_ < 2; half_++) {
            const size_t row = (size_t)(bm + rbase + i * 16 + g + half_ * 8);
            OT* crow = C + row * N + bn;
            const float* rrow = (EPI == 2) ? (res + row * N + bn) : nullptr;
            #pragma unroll
            for (int j = 0; j < 8; j++) {
                const int col = cbase + j * 8 + 2 * tig;
                float2 b2 = *(const float2*)(bias + bn + col);
                float vx = acc[i][j][half_ * 2 + 0] + b2.x;
                float vy = acc[i][j][half_ * 2 + 1] + b2.y;
                if (EPI == 1) { vx = gelu_exact(vx); vy = gelu_exact(vy); }
                if constexpr (EPI == 2) {
                    float2 r2 = *(const float2*)(rrow + col);
                    float2 o; o.x = vx + r2.x; o.y = vy + r2.y;
                    *(float2*)((float*)crow + col) = o;
                } else {
                    __half2 hv = __floats2half2_rn(vx, vy);
                    *(__half2*)((__half*)crow + col) = hv;
                }
            }
        }
    }
}

// ---------------------------------------------------------------------------
// LayerNorm: one block per row, 256 threads * 4 floats; fp16 output
// ---------------------------------------------------------------------------
__global__ void ln_kernel(const float* __restrict__ x,
                          const float* __restrict__ gamma,
                          const float* __restrict__ beta,
                          __half* __restrict__ y)
{
    const int row = blockIdx.x;
    const int t = threadIdx.x;
    const float4* xr = (const float4*)(x + (size_t)row * DMODEL);
    float4 xv = xr[t];

    __shared__ float red[8];
    __shared__ float stats[2];

    float s = xv.x + xv.y + xv.z + xv.w;
    #pragma unroll
    for (int o = 16; o > 0; o >>= 1) s += __shfl_xor_sync(0xffffffffu, s, o);
    if ((t & 31) == 0) red[t >> 5] = s;
    __syncthreads();
    if (t == 0) {
        float tot = 0.f;
        #pragma unroll
        for (int i = 0; i < 8; i++) tot += red[i];
        stats[0] = tot * (1.0f / DMODEL);
    }
    __syncthreads();
    const float mean = stats[0];

    float dx = xv.x - mean, dy = xv.y - mean, dz = xv.z - mean, dw = xv.w - mean;
    float s2 = dx*dx + dy*dy + dz*dz + dw*dw;
    #pragma unroll
    for (int o = 16; o > 0; o >>= 1) s2 += __shfl_xor_sync(0xffffffffu, s2, o);
    if ((t & 31) == 0) red[t >> 5] = s2;
    __syncthreads();
    if (t == 0) {
        float tot = 0.f;
        #pragma unroll
        for (int i = 0; i < 8; i++) tot += red[i];
        stats[1] = rsqrtf(tot * (1.0f / DMODEL) + LN_EPS);
    }
    __syncthreads();
    const float rstd = stats[1];

    float4 g4 = ((const float4*)gamma)[t];
    float4 b4 = ((const float4*)beta)[t];
    __half2 h0 = __floats2half2_rn(dx * rstd * g4.x + b4.x, dy * rstd * g4.y + b4.y);
    __half2 h1 = __floats2half2_rn(dz * rstd * g4.z + b4.z, dw * rstd * g4.w + b4.w);
    uint2 o; o.x = *(uint32_t*)&h0; o.y = *(uint32_t*)&h1;
    ((uint2*)(y + (size_t)row * DMODEL))[t] = o;
}

// ---------------------------------------------------------------------------
// Flash attention v2-style (causal), fp16 mma, register-resident softmax.
// Block = (q-tile 128, head, batch); 8 warps; warp owns 16 q-rows x full kv.
// S lives in mma accumulators; P converts in-register to the PV A-operand.
// K, V natural [k][d] in SMEM, cp.async double-buffered; PV B-frags via
// ldmatrix.x4.trans.  No score SMEM, 2 syncs per kv-tile.
// SMEM (halves): Qs[128*72]@0, K0@9216, K1@13824, V0@18432, V1@23040
// ---------------------------------------------------------------------------
#define ATT_SMEM_BYTES (27648 * 2)

__global__ __launch_bounds__(256)
void attn_fa2(const __half* __restrict__ qkv, __half* __restrict__ out)
{
    extern __shared__ __half sh[];
    const uint32_t sb = smem_u32(sh);

    const int qt = 15 - (int)blockIdx.x;     // big tiles first
    const int h  = blockIdx.y;
    const int b  = blockIdx.z;
    const int tid = threadIdx.x;
    const int w = tid >> 5, lane = tid & 31;
    const int g = lane >> 2, t = lane & 3;

    const size_t rs = D3;
    const __half* qbase = qkv + (size_t)b * SEQ * rs + h * HDIM;
    const __half* kbase = qbase + DMODEL;
    const __half* vbase = qbase + 2 * DMODEL;

    // ---- stage Q tile (scaled 1/8) into SMEM ----
    {
        const __half2 s2 = __float2half2_rn(0.125f);
        #pragma unroll
        for (int p = 0; p < 4; p++) {
            const int idx = p * 256 + tid;        // 1024 uint4
            const int row = idx >> 3;
            const int ch = idx & 7;
            uint4 v = *(const uint4*)(qbase + (size_t)(qt * 128 + row) * rs + ch * 8);
            __half2* hv = (__half2*)&v;
            hv[0] = __hmul2(hv[0], s2); hv[1] = __hmul2(hv[1], s2);
            hv[2] = __hmul2(hv[2], s2); hv[3] = __hmul2(hv[3], s2);
            *(uint4*)(sh + row * 72 + ch * 8) = v;
        }
    }
    __syncthreads();

    // ---- hoist Q fragments to registers (warp rows 16w..16w+16) ----
    uint32_t qa[4][4];
    {
        const uint32_t* Qu = (const uint32_t*)sh;
        const int r0 = 16 * w + g;
        #pragma unroll
        for (int ks = 0; ks < 4; ks++) {
            const int kk = ks * 8;
            qa[ks][0] = Qu[r0 * 36 + kk + t];
            qa[ks][1] = Qu[(r0 + 8) * 36 + kk + t];
            qa[ks][2] = Qu[r0 * 36 + kk + t + 4];
            qa[ks][3] = Qu[(r0 + 8) * 36 + kk + t + 4];
        }
    }
    __syncthreads();     // Qs SMEM no longer read after this... (kept separate anyway)

    // ldmatrix per-lane address parts for V [k][d] tiles (stride 72 halves)
    const int mi = lane >> 3;                 // matrix index 0..3
    const int rp = ((mi & 1) << 3) + (lane & 7);   // k-row part
    const int cp = (mi >> 1);                      // j-offset part
    const uint32_t v_laneoff = (uint32_t)(rp * 72 + cp * 8) * 2;

    const int qg0 = qt * 128 + 16 * w + g;    // this lane's q rows
    const int qg1 = qg0 + 8;

    float oacc[8][4];
    #pragma unroll
    for (int j = 0; j < 8; j++)
        #pragma unroll
        for (int r = 0; r < 4; r++) oacc[j][r] = 0.f;
    float m0 = -1e30f, m1 = -1e30f, l0 = 0.f, l1 = 0.f;

    const int nk = 2 * qt + 2;

    // K/V tile loader via cp.async (natural layout)
    auto load_kv = [&](int kt, int buf) {
        #pragma unroll
        for (int p = 0; p < 2; p++) {
            const int idx = p * 256 + tid;    // 512 uint4 each
            const int row = idx >> 3;
            const int ch = idx & 7;
            const size_t goff = (size_t)(kt * 64 + row) * rs + ch * 8;
            const uint32_t soff = (uint32_t)(row * 72 + ch * 8) * 2;
            cp_async16(sb + (9216 + buf * 4608) * 2 + soff, kbase + goff);
            cp_async16(sb + (18432 + buf * 4608) * 2 + soff, vbase + goff);
        }
    };

    load_kv(0, 0);
    cp_commit();

    for (int kt = 0; kt < nk; kt++) {
        const int buf = kt & 1;
        if (kt + 1 < nk) {
            load_kv(kt + 1, buf ^ 1);
            cp_commit();
            cp_wait<1>();
        } else {
            cp_wait<0>();
        }
        __syncthreads();

        const uint32_t* Ku = (const uint32_t*)(sh + 9216 + buf * 4608);
        const uint32_t vtile = sb + (18432 + buf * 4608) * 2;

        // ---- S = Q K^T ----
        float sacc[8][4];
        #pragma unroll
        for (int j = 0; j < 8; j++)
            #pragma unroll
            for (int r = 0; r < 4; r++) sacc[j][r] = 0.f;

        #pragma unroll
        for (int ks = 0; ks < 4; ks++) {
            const int kk = ks * 8;
            #pragma unroll
            for (int j = 0; j < 8; j++) {
                const int c0 = j * 8 + g;
                uint32_t b0 = Ku[c0 * 36 + kk + t];
                uint32_t b1 = Ku[c0 * 36 + kk + t + 4];
                mma_h(sacc[j], qa[ks][0], qa[ks][1], qa[ks][2], qa[ks][3], b0, b1);
            }
        }

        // ---- causal mask (only the two diagonal tiles need it) ----
        if (kt >= 2 * qt) {
            #pragma unroll
            for (int j = 0; j < 8; j++) {
                const int k0 = kt * 64 + j * 8 + 2 * t;
                if (k0     > qg0) sacc[j][0] = -1e30f;
                if (k0 + 1 > qg0) sacc[j][1] = -1e30f;
                if (k0     > qg1) sacc[j][2] = -1e30f;
                if (k0 + 1 > qg1) sacc[j][3] = -1e30f;
            }
        }

        // ---- register softmax (online) ----
        float mx0 = -1e30f, mx1 = -1e30f;
        #pragma unroll
        for (int j = 0; j < 8; j++) {
            mx0 = fmaxf(mx0, fmaxf(sacc[j][0], sacc[j][1]));
            mx1 = fmaxf(mx1, fmaxf(sacc[j][2], sacc[j][3]));
        }
        mx0 = fmaxf(mx0, __shfl_xor_sync(0xffffffffu, mx0, 1));
        mx0 = fmaxf(mx0, __shfl_xor_sync(0xffffffffu, mx0, 2));
        mx1 = fmaxf(mx1, __shfl_xor_sync(0xffffffffu, mx1, 1));
        mx1 = fmaxf(mx1, __shfl_xor_sync(0xffffffffu, mx1, 2));

        const float m0n = fmaxf(m0, mx0);
        const float m1n = fmaxf(m1, mx1);
        const float f0 = __expf(m0 - m0n);
        const float f1 = __expf(m1 - m1n);
        m0 = m0n; m1 = m1n;

        uint32_t pa[8][2];
        float s0 = 0.f, s1 = 0.f;
        #pragma unroll
        for (int j = 0; j < 8; j++) {
            float p0 = __expf(sacc[j][0] - m0);
            float p1 = __expf(sacc[j][1] - m0);
            float p2 = __expf(sacc[j][2] - m1);
            float p3 = __expf(sacc[j][3] - m1);
            s0 += p0 + p1; s1 += p2 + p3;
            __half2 h01 = __floats2half2_rn(p0, p1);
            __half2 h23 = __floats2half2_rn(p2, p3);
            pa[j][0] = *(uint32_t*)&h01;
            pa[j][1] = *(uint32_t*)&h23;
        }
        s0 += __shfl_xor_sync(0xffffffffu, s0, 1);
        s0 += __shfl_xor_sync(0xffffffffu, s0, 2);
        s1 += __shfl_xor_sync(0xffffffffu, s1, 1);
        s1 += __shfl_xor_sync(0xffffffffu, s1, 2);
        l0 = l0 * f0 + s0;
        l1 = l1 * f1 + s1;

        #pragma unroll
        for (int j = 0; j < 8; j++) {
            oacc[j][0] *= f0; oacc[j][1] *= f0;
            oacc[j][2] *= f1; oacc[j][3] *= f1;
        }

        // ---- O += P V  (A from registers, B via ldmatrix.trans) ----
        #pragma unroll
        for (int ks = 0; ks < 4; ks++) {
            const uint32_t a0 = pa[2 * ks][0];
            const uint32_t a1 = pa[2 * ks][1];
            const uint32_t a2 = pa[2 * ks + 1][0];
            const uint32_t a3 = pa[2 * ks + 1][1];
            #pragma unroll
            for (int c = 0; c < 4; c++) {
                uint32_t b0, b1, b2, b3;
                ldsm_x4_trans(b0, b1, b2, b3,
                              vtile + v_laneoff + (uint32_t)(ks * 2304 + c * 32));
                mma_h(oacc[2 * c],     a0, a1, a2, a3, b0, b1);
                mma_h(oacc[2 * c + 1], a0, a1, a2, a3, b2, b3);
            }
        }
        __syncthreads();   // all warps done with buf before it is overwritten
    }

    // ---- write O / l ----
    const float inv0 = 1.0f / l0;
    const float inv1 = 1.0f / l1;
    const size_t row0 = (size_t)(b * SEQ + qg0);
    #pragma unroll
    for (int j = 0; j < 8; j++) {
        const int col = h * HDIM + j * 8 + 2 * t;
        __half2 o0 = __floats2half2_rn(oacc[j][0] * inv0, oacc[j][1] * inv0);
        __half2 o1 = __floats2half2_rn(oacc[j][2] * inv1, oacc[j][3] * inv1);
        *(__half2*)(out + row0 * DMODEL + col) = o0;
        *(__half2*)(out + (row0 + 8) * DMODEL + col) = o1;
    }
}

// ---------------------------------------------------------------------------
// Launch
// ---------------------------------------------------------------------------
extern "C" void kernel_launch(void* const* d_in, const int* in_sizes, int n_in,
                              void* d_out, int out_size)
{
    const float* x     = (const float*)d_in[0];
    const float* ln1_g = (const float*)d_in[1];
    const float* ln1_b = (const float*)d_in[2];
    const float* qkv_w = (const float*)d_in[3];
    const float* qkv_b = (const float*)d_in[4];
    const float* out_w = (const float*)d_in[5];
    const float* out_b = (const float*)d_in[6];
    const float* ln2_g = (const float*)d_in[7];
    const float* ln2_b = (const float*)d_in[8];
    const float* fc1_w = (const float*)d_in[9];
    const float* fc1_b = (const float*)d_in[10];
    const float* fc2_w = (const float*)d_in[11];
    const float* fc2_b = (const float*)d_in[12];
    float* out = (float*)d_out;

    __half *h, *qkv, *attn, *ff, *wc;
    cudaGetSymbolAddress((void**)&h,    g_h);
    cudaGetSymbolAddress((void**)&qkv,  g_qkv);
    cudaGetSymbolAddress((void**)&attn, g_attn);
    cudaGetSymbolAddress((void**)&ff,   g_ff);
    cudaGetSymbolAddress((void**)&wc,   g_wc);

    __half* wq = wc;                 // 3M elems
    __half* wo = wc + 3145728;       // 1M
    __half* w1 = wc + 4194304;       // 4M
    __half* w2 = wc + 8388608;       // 4M

    cudaFuncSetAttribute(attn_fa2,
                         cudaFuncAttributeMaxDynamicSharedMemorySize, ATT_SMEM_BYTES);
    cudaFuncSetAttribute((gemm_h<0, __half>),
                         cudaFuncAttributeMaxDynamicSharedMemorySize, GEMM_SMEM_BYTES);
    cudaFuncSetAttribute((gemm_h<1, __half>),
                         cudaFuncAttributeMaxDynamicSharedMemorySize, GEMM_SMEM_BYTES);
    cudaFuncSetAttribute((gemm_h<2, float>),
                         cudaFuncAttributeMaxDynamicSharedMemorySize, GEMM_SMEM_BYTES);

    // 0) convert all weights to fp16 (one launch)
    cvt_all<<<6144, 256>>>(qkv_w, out_w, fc1_w, fc2_w, wc);

    // 1) h = fp16(LN1(x))
    ln_kernel<<<M_ROWS, 256>>>(x, ln1_g, ln1_b, h);

    // 2) qkv = h @ wq^T + qkv_b   (fp16 out)
    gemm_h<0, __half><<<dim3(D3 / 256, M_ROWS / 128), 256, GEMM_SMEM_BYTES>>>(
        h, wq, qkv_b, nullptr, qkv, M_ROWS, D3, DMODEL);

    // 3) attn = fp16(causal_flash_attention(qkv))
    attn_fa2<<<dim3(SEQ / 128, NHEADS, 2), 256, ATT_SMEM_BYTES>>>(qkv, attn);

    // 4) x1 = attn @ wo^T + out_b + x   (fp32 out)
    gemm_h<2, float><<<dim3(DMODEL / 256, M_ROWS / 128), 256, GEMM_SMEM_BYTES>>>(
        attn, wo, out_b, x, out, M_ROWS, DMODEL, DMODEL);

    // 5) h = fp16(LN2(x1))
    ln_kernel<<<M_ROWS, 256>>>(out, ln2_g, ln2_b, h);

    // 6) ff = fp16(gelu(h @ w1^T + fc1_b))
    gemm_h<1, __half><<<dim3(DFF / 256, M_ROWS / 128), 256, GEMM_SMEM_BYTES>>>(
        h, w1, fc1_b, nullptr, ff, M_ROWS, DFF, DMODEL);

    // 7) out = ff @ w2^T + fc2_b + x1   (fp32 out, in-place residual)
    gemm_h<2, float><<<dim3(DMODEL / 256, M_ROWS / 128), 256, GEMM_SMEM_BYTES>>>(
        ff, w2, fc2_b, out, out, M_ROWS, DMODEL, DFF);
}